// round 1
// baseline (speedup 1.0000x reference)
#include <cuda_runtime.h>

// Problem constants
#define Bk 16
#define Dk 256
#define Tk 2048
#define Kk 8192
#define Nk 32768            // B*T
#define QCOUNT 8388608      // B*D*T
#define KSPLIT 8
#define CODES_PER_SPLIT (Kk / KSPLIT)   // 1024

// Scratch (no allocations allowed -> __device__ globals)
__device__ float g_enorm[Kk];
__device__ float g_znorm[Nk];
__device__ float g_bestd[KSPLIT * Nk];
__device__ int   g_besti[KSPLIT * Nk];
__device__ int   g_idx[Nk];
__device__ float g_losspart[QCOUNT / 1024];

// ---------------- emb row norms: one warp per code ----------------
__global__ void enorm_kernel(const float* __restrict__ emb) {
    int warp = (blockIdx.x * blockDim.x + threadIdx.x) >> 5;
    int lane = threadIdx.x & 31;
    if (warp >= Kk) return;
    const float* row = emb + (size_t)warp * Dk;
    float s = 0.f;
#pragma unroll
    for (int i = 0; i < Dk; i += 32) { float v = row[i + lane]; s += v * v; }
#pragma unroll
    for (int o = 16; o > 0; o >>= 1) s += __shfl_down_sync(0xffffffffu, s, o);
    if (lane == 0) g_enorm[warp] = s;
}

// ---------------- z row norms: coalesced along t ----------------
__global__ void znorm_kernel(const float* __restrict__ z) {
    int n = blockIdx.x * blockDim.x + threadIdx.x;   // blockDim = 128
    int b = n >> 11, t = n & 2047;
    const float* zp = z + (size_t)b * (Dk * Tk) + t;
    float s = 0.f;
#pragma unroll 8
    for (int d = 0; d < Dk; d++) { float v = zp[(size_t)d * Tk]; s += v * v; }
    g_znorm[n] = s;
}

// ---------------- fused distance GEMM + running argmin ----------------
// grid = (Nk/128, KSPLIT); block = 256 threads; 8x8 micro-tiles
#define BM 128
#define BN 128
#define BKD 16
__global__ __launch_bounds__(256)
void dist_argmin_kernel(const float* __restrict__ z, const float* __restrict__ emb) {
    __shared__ float As[BKD][BM];
    __shared__ float Bs[BKD][BN + 4];
    __shared__ float En[BN];
    __shared__ float Rd[BM][17];
    __shared__ int   Ri[BM][17];

    int rowBase = blockIdx.x * BM;              // BM divides T -> single b per tile
    int b = rowBase >> 11, t0 = rowBase & 2047;
    const float* zb = z + (size_t)b * (Dk * Tk) + t0;
    int sliceBase = blockIdx.y * CODES_PER_SPLIT;
    int tid = threadIdx.x;
    int tx = tid & 15, ty = tid >> 4;

    float zn[8];
#pragma unroll
    for (int i = 0; i < 8; i++) zn[i] = g_znorm[rowBase + ty * 8 + i];

    float bestd[8]; int besti[8];
#pragma unroll
    for (int i = 0; i < 8; i++) { bestd[i] = 3.4e38f; besti[i] = 0x7fffffff; }

    for (int cc = 0; cc < CODES_PER_SPLIT / BN; cc++) {
        int codeBase = sliceBase + cc * BN;
        if (tid < BN) En[tid] = g_enorm[codeBase + tid];

        float acc[8][8];
#pragma unroll
        for (int i = 0; i < 8; i++)
#pragma unroll
            for (int j = 0; j < 8; j++) acc[i][j] = 0.f;

        for (int d0 = 0; d0 < Dk; d0 += BKD) {
            __syncthreads();
            // A tile: coalesced along t (128 contiguous floats per d)
#pragma unroll
            for (int i = 0; i < 8; i++) {
                int idx = tid + i * 256;
                int kk = idx >> 7, r = idx & 127;
                As[kk][r] = zb[(size_t)(d0 + kk) * Tk + r];
            }
            // B tile: transpose-on-store, padded to break bank conflicts
#pragma unroll
            for (int i = 0; i < 8; i++) {
                int idx = tid + i * 256;
                int kk = idx & 15, c = idx >> 4;
                Bs[kk][c] = emb[(size_t)(codeBase + c) * Dk + d0 + kk];
            }
            __syncthreads();
#pragma unroll
            for (int kk = 0; kk < BKD; kk++) {
                float a[8], bb[8];
#pragma unroll
                for (int i = 0; i < 8; i++) a[i] = As[kk][ty * 8 + i];
#pragma unroll
                for (int j = 0; j < 8; j++) bb[j] = Bs[kk][tx * 8 + j];
#pragma unroll
                for (int i = 0; i < 8; i++)
#pragma unroll
                    for (int j = 0; j < 8; j++)
                        acc[i][j] += a[i] * bb[j];
            }
        }
        __syncthreads();
        // epilogue: replicate reference rounding d = fl(fl(zz+en) - 2*dot)
#pragma unroll
        for (int j = 0; j < 8; j++) {
            int k = codeBase + tx * 8 + j;
            float en = En[tx * 8 + j];
#pragma unroll
            for (int i = 0; i < 8; i++) {
                float s1 = zn[i] + en;
                float dcur = s1 - 2.0f * acc[i][j];   // FFMA: exact 2*acc, same rounding
                if (dcur < bestd[i] || (dcur == bestd[i] && k < besti[i])) {
                    bestd[i] = dcur; besti[i] = k;
                }
            }
        }
        __syncthreads();   // before En is overwritten next chunk
    }

    // cross-thread lex-min per row (16 column-groups share each row)
#pragma unroll
    for (int i = 0; i < 8; i++) {
        Rd[ty * 8 + i][tx] = bestd[i];
        Ri[ty * 8 + i][tx] = besti[i];
    }
    __syncthreads();
    if (tid < BM) {
        float bd = 3.4e38f; int bi = 0x7fffffff;
#pragma unroll
        for (int x = 0; x < 16; x++) {
            float dv = Rd[tid][x]; int iv = Ri[tid][x];
            if (dv < bd || (dv == bd && iv < bi)) { bd = dv; bi = iv; }
        }
        g_bestd[(size_t)blockIdx.y * Nk + rowBase + tid] = bd;
        g_besti[(size_t)blockIdx.y * Nk + rowBase + tid] = bi;
    }
}

// ---------------- combine split-K partials ----------------
__global__ void combine_kernel(float* __restrict__ idx_out) {
    int n = blockIdx.x * blockDim.x + threadIdx.x;
    if (n >= Nk) return;
    float bd = 3.4e38f; int bi = 0x7fffffff;
#pragma unroll
    for (int s = 0; s < KSPLIT; s++) {
        float dv = g_bestd[(size_t)s * Nk + n];
        int   iv = g_besti[(size_t)s * Nk + n];
        if (dv < bd || (dv == bd && iv < bi)) { bd = dv; bi = iv; }
    }
    g_idx[n] = bi;
    if (idx_out) idx_out[n] = (float)bi;
}

// ---------------- gather quantized + per-block loss partials ----------------
__global__ __launch_bounds__(1024)
void quant_loss_kernel(const float* __restrict__ z, const float* __restrict__ emb,
                       float* __restrict__ qout) {
    __shared__ float red[1024];
    int g = blockIdx.x * 1024 + threadIdx.x;    // linear index into [B][D][T]
    int t = g & 2047;
    int d = (g >> 11) & 255;
    int b = g >> 19;
    int n = b * 2048 + t;
    float q = emb[(size_t)g_idx[n] * Dk + d];   // random-row gather, L2-resident (8MB)
    qout[g] = q;
    float diff = q - z[g];
    red[threadIdx.x] = diff * diff;
    __syncthreads();
#pragma unroll
    for (int o = 512; o > 0; o >>= 1) {
        if (threadIdx.x < o) red[threadIdx.x] += red[threadIdx.x + o];
        __syncthreads();
    }
    if (threadIdx.x == 0) g_losspart[blockIdx.x] = red[0];
}

// ---------------- deterministic final loss reduce ----------------
__global__ void loss_kernel(float* __restrict__ loss_out) {
    __shared__ float red[256];
    float s = 0.f;
    for (int i = threadIdx.x; i < QCOUNT / 1024; i += 256) s += g_losspart[i];
    red[threadIdx.x] = s;
    __syncthreads();
#pragma unroll
    for (int o = 128; o > 0; o >>= 1) {
        if (threadIdx.x < o) red[threadIdx.x] += red[threadIdx.x + o];
        __syncthreads();
    }
    // loss = q_latent + 0.25*e_latent, both equal mean((q-z)^2) forward
    if (threadIdx.x == 0) loss_out[0] = 1.25f * (red[0] / (float)QCOUNT);
}

extern "C" void kernel_launch(void* const* d_in, const int* in_sizes, int n_in,
                              void* d_out, int out_size) {
    const float* z   = (const float*)d_in[0];
    const float* emb = (const float*)d_in[1];
    float* out = (float*)d_out;

    float* qout     = out;
    float* loss_out = nullptr;
    float* idx_out  = nullptr;
    if (out_size >= QCOUNT + 1 + Nk) {          // [quantized | loss | idx]
        loss_out = out + QCOUNT;
        idx_out  = out + QCOUNT + 1;
    } else if (out_size == QCOUNT + Nk) {       // [quantized | idx]
        idx_out = out + QCOUNT;
    } else if (out_size == QCOUNT + 1) {        // [quantized | loss]
        loss_out = out + QCOUNT;
    }                                           // else: quantized only

    enorm_kernel<<<Kk / 8, 256>>>(emb);
    znorm_kernel<<<Nk / 128, 128>>>(z);
    dist_argmin_kernel<<<dim3(Nk / BM, KSPLIT), 256>>>(z, emb);
    combine_kernel<<<Nk / 256, 256>>>(idx_out);
    quant_loss_kernel<<<QCOUNT / 1024, 1024>>>(z, emb, qout);
    if (loss_out) loss_kernel<<<1, 256>>>(loss_out);
}

// round 3
// speedup vs baseline: 4.0790x; 4.0790x over previous
#include <cuda_runtime.h>
#include <cuda_bf16.h>
#include <cstdint>

// ---------------- problem constants ----------------
#define Dk 256
#define Tk 2048
#define Bk 16
#define Kk 8192
#define Nk 32768            // B*T
#define QCOUNT 8388608      // B*D*T

// ---------------- pass1 GEMM config ----------------
#define GM 128              // rows per CTA
#define GN 128              // codes per chunk
#define NCHUNKS 64          // 8192/128
#define NSTAGES_TOT 1024    // 64 chunks * 16 ksteps
#define A_STRIDE 264        // 256 + 8 pad (elements)
#define B_STRIDE 24         // 16 + 8 pad (elements)

// smem layout (bytes)
#define SM_A   0
#define SM_B   67584                    // 128*264*2
#define SM_EN  (SM_B + 4*128*B_STRIDE*2)   // 67584+24576 = 92160
#define SM_RED (SM_EN + 512)            // 92672
#define SMEM_TOTAL (SM_RED + 2048)      // 94720

#define TAU 2.5e-4f

// ---------------- device scratch (no allocs allowed) ----------------
__device__ __align__(16) __nv_bfloat16 g_A[(size_t)Nk * Dk];   // z transposed bf16 [n][d], 16MB
__device__ __align__(16) float         g_zt[(size_t)Nk * Dk];  // z transposed fp32 [n][d], 33.5MB
__device__ __align__(16) __nv_bfloat16 g_Bm[(size_t)Kk * Dk];  // emb bf16 [k][d], 4MB
__device__ __align__(16) float g_gmin[(size_t)Nk * 256];       // per-row per-32-code-group min, 32MB
__device__ float g_enorm[Kk];
__device__ int   g_idx[Nk];
__device__ float g_losspart[QCOUNT / 1024];

// ---------------- asm helpers ----------------
__device__ __forceinline__ uint32_t smem_u32(const void* p) {
    uint32_t a;
    asm("{ .reg .u64 t; cvta.to.shared.u64 t, %1; cvt.u32.u64 %0, t; }" : "=r"(a) : "l"(p));
    return a;
}
__device__ __forceinline__ void cp_async16(uint32_t dst, const void* src) {
    asm volatile("cp.async.cg.shared.global [%0], [%1], 16;"
                 :: "r"(dst), "l"(__cvta_generic_to_global(src)) : "memory");
}
__device__ __forceinline__ void cp_commit() {
    asm volatile("cp.async.commit_group;" ::: "memory");
}
__device__ __forceinline__ void cp_wait2() {
    asm volatile("cp.async.wait_group 2;" ::: "memory");
}
__device__ __forceinline__ void ldsm_x4(uint32_t& r0, uint32_t& r1, uint32_t& r2, uint32_t& r3,
                                        uint32_t addr) {
    asm volatile("ldmatrix.sync.aligned.m8n8.x4.shared.b16 {%0,%1,%2,%3}, [%4];"
                 : "=r"(r0), "=r"(r1), "=r"(r2), "=r"(r3) : "r"(addr));
}
__device__ __forceinline__ void mma_bf16(float* c, uint32_t a0, uint32_t a1, uint32_t a2,
                                         uint32_t a3, uint32_t b0, uint32_t b1) {
    asm volatile("mma.sync.aligned.m16n8k16.row.col.f32.bf16.bf16.f32 "
                 "{%0,%1,%2,%3}, {%4,%5,%6,%7}, {%8,%9}, {%0,%1,%2,%3};"
                 : "+f"(c[0]), "+f"(c[1]), "+f"(c[2]), "+f"(c[3])
                 : "r"(a0), "r"(a1), "r"(a2), "r"(a3), "r"(b0), "r"(b1));
}

// ---------------- prep: emb row norms ----------------
__global__ void enorm_kernel(const float* __restrict__ emb) {
    int warp = (blockIdx.x * blockDim.x + threadIdx.x) >> 5;
    int lane = threadIdx.x & 31;
    if (warp >= Kk) return;
    const float* row = emb + (size_t)warp * Dk;
    float s = 0.f;
#pragma unroll
    for (int i = 0; i < Dk; i += 32) { float v = row[i + lane]; s += v * v; }
#pragma unroll
    for (int o = 16; o > 0; o >>= 1) s += __shfl_down_sync(0xffffffffu, s, o);
    if (lane == 0) g_enorm[warp] = s;
}

// ---------------- prep: transpose z -> [n][d] (bf16 + fp32) ----------------
__global__ void prepA_kernel(const float* __restrict__ z) {
    __shared__ float tile[32][33];
    int b = blockIdx.x >> 6;
    int t0 = (blockIdx.x & 63) * 32;
    int d0 = blockIdx.y * 32;
    int tx = threadIdx.x;
#pragma unroll
    for (int i = threadIdx.y; i < 32; i += 8)
        tile[i][tx] = z[((size_t)b * Dk + d0 + i) * Tk + t0 + tx];
    __syncthreads();
#pragma unroll
    for (int i = threadIdx.y; i < 32; i += 8) {
        int n = b * Tk + t0 + i;
        float v = tile[tx][i];
        g_A[(size_t)n * Dk + d0 + tx] = __float2bfloat16(v);
        g_zt[(size_t)n * Dk + d0 + tx] = v;
    }
}

// ---------------- prep: emb -> bf16 ----------------
__global__ void prepB_kernel(const float* __restrict__ emb) {
    int i = blockIdx.x * 256 + threadIdx.x;
    g_Bm[i] = __float2bfloat16(emb[i]);
}

// ---------------- pass1: bf16 HMMA GEMM + per-group min ----------------
__global__ __launch_bounds__(256, 2)
void pass1_gemm(void) {
    extern __shared__ __align__(16) char smem[];
    uint32_t sb = smem_u32(smem);
    __nv_bfloat16* A_sm = (__nv_bfloat16*)(smem + SM_A);
    float* en_sm = (float*)(smem + SM_EN);
    float* red_sm = (float*)(smem + SM_RED);   // [128][4]

    int tid = threadIdx.x;
    int lane = tid & 31;
    int wid = tid >> 5;
    int warpN = wid & 3;      // 4 n-warps (32 cols each)
    int warpM = wid >> 2;     // 2 m-warps (64 rows each)
    int rowBase = blockIdx.x * GM;

    // ---- issue A load (resident) + B stages 0..2 ----
    {
        const __nv_bfloat16* Ag = g_A + (size_t)rowBase * Dk;
#pragma unroll
        for (int i = 0; i < 16; i++) {
            int idx = tid + i * 256;               // 4096 x 16B
            int r = idx >> 5, ch = idx & 31;
            cp_async16(sb + SM_A + (r * A_STRIDE + ch * 8) * 2, Ag + (size_t)r * Dk + ch * 8);
        }
        // B stage 0 (chunk 0, ks 0) in same group as A
        {
            int r = tid >> 1, half = tid & 1;
            cp_async16(sb + SM_B + (r * B_STRIDE + half * 8) * 2, g_Bm + (size_t)r * Dk + half * 8);
        }
        cp_commit();   // G0 = {A, B0}
#pragma unroll
        for (int s = 1; s <= 2; s++) {
            int r = tid >> 1, half = tid & 1;
            cp_async16(sb + SM_B + s * (128 * B_STRIDE * 2) + (r * B_STRIDE + half * 8) * 2,
                       g_Bm + (size_t)r * Dk + s * 16 + half * 8);
            cp_commit();   // G1, G2
        }
    }

    float acc[4][4][4];
    int c_cur = 0;

    for (int s = 0; s < NSTAGES_TOT; s++) {
        int c = s >> 4;
        int ks = s & 15;
        cp_wait2();
        __syncthreads();

        // issue stage s+3
        if (s + 3 < NSTAGES_TOT) {
            int s3 = s + 3;
            int cc = s3 >> 4, kk = s3 & 15;
            int buf = s3 & 3;
            int r = tid >> 1, half = tid & 1;
            cp_async16(sb + SM_B + buf * (128 * B_STRIDE * 2) + (r * B_STRIDE + half * 8) * 2,
                       g_Bm + ((size_t)cc * GN + r) * Dk + kk * 16 + half * 8);
        }
        cp_commit();

        if (ks == 0) {
            c_cur = c;
#pragma unroll
            for (int i = 0; i < 4; i++)
#pragma unroll
                for (int j = 0; j < 4; j++)
#pragma unroll
                    for (int e = 0; e < 4; e++) acc[i][j][e] = 0.f;
            if (tid < 128) en_sm[tid] = g_enorm[c * GN + tid];
        }

        // ---- compute stage s ----
        {
            int buf = s & 3;
            uint32_t af[4][4];
            uint32_t bf[4][2];
            // A frags: 4 m-tiles
#pragma unroll
            for (int mt = 0; mt < 4; mt++) {
                int row = warpM * 64 + mt * 16 + (lane & 15);
                int col = ks * 16 + (lane >> 4) * 8;
                ldsm_x4(af[mt][0], af[mt][1], af[mt][2], af[mt][3],
                        sb + SM_A + (row * A_STRIDE + col) * 2);
            }
            // B frags: 2 x ldsm.x4 -> 4 n-tiles
#pragma unroll
            for (int pr = 0; pr < 2; pr++) {
                int nrow = warpN * 32 + pr * 16 + (lane & 7) + ((lane & 16) ? 8 : 0);
                int ncol = (lane & 8);   // 0 or 8
                uint32_t r0, r1, r2, r3;
                ldsm_x4(r0, r1, r2, r3,
                        sb + SM_B + buf * (128 * B_STRIDE * 2) + (nrow * B_STRIDE + ncol) * 2);
                bf[pr * 2 + 0][0] = r0; bf[pr * 2 + 0][1] = r1;
                bf[pr * 2 + 1][0] = r2; bf[pr * 2 + 1][1] = r3;
            }
#pragma unroll
            for (int mt = 0; mt < 4; mt++)
#pragma unroll
                for (int nt = 0; nt < 4; nt++)
                    mma_bf16(acc[mt][nt], af[mt][0], af[mt][1], af[mt][2], af[mt][3],
                             bf[nt][0], bf[nt][1]);
        }

        // ---- end-of-chunk epilogue ----
        if (ks == 15) {
            float en8[8];
#pragma unroll
            for (int nt = 0; nt < 4; nt++) {
#pragma unroll
                for (int e = 0; e < 2; e++)
                    en8[nt * 2 + e] = en_sm[warpN * 32 + nt * 8 + (lane & 3) * 2 + e];
            }
#pragma unroll
            for (int mt = 0; mt < 4; mt++) {
#pragma unroll
                for (int h = 0; h < 2; h++) {
                    float v = 3.4e38f;
#pragma unroll
                    for (int nt = 0; nt < 4; nt++) {
#pragma unroll
                        for (int e = 0; e < 2; e++) {
                            float d = fmaf(-2.f, acc[mt][nt][h * 2 + e], en8[nt * 2 + e]);
                            v = fminf(v, d);
                        }
                    }
                    v = fminf(v, __shfl_xor_sync(0xffffffffu, v, 1));
                    v = fminf(v, __shfl_xor_sync(0xffffffffu, v, 2));
                    if ((lane & 3) == 0) {
                        int row = warpM * 64 + mt * 16 + (lane >> 2) + h * 8;
                        red_sm[row * 4 + warpN] = v;
                    }
                }
            }
            __syncthreads();
            if (tid < 128) {
                float4 v = *(float4*)(red_sm + tid * 4);
                *(float4*)(g_gmin + (size_t)(rowBase + tid) * 256 + c_cur * 4) = v;
            }
            // next iteration's __syncthreads protects red_sm reuse
        }
    }
}

// ---------------- pass2: exact fp32 refine over candidate groups ----------------
__global__ __launch_bounds__(256)
void refine_kernel(const float* __restrict__ emb, float* __restrict__ idx_out) {
    int lane = threadIdx.x & 31;
    int n = blockIdx.x * 8 + (threadIdx.x >> 5);

    // exact z row (fp32)
    float zr[8];
#pragma unroll
    for (int i = 0; i < 8; i++) zr[i] = g_zt[(size_t)n * Dk + lane + 32 * i];
    float zn = 0.f;
#pragma unroll
    for (int i = 0; i < 8; i++) zn = fmaf(zr[i], zr[i], zn);
#pragma unroll
    for (int o = 16; o > 0; o >>= 1) zn += __shfl_xor_sync(0xffffffffu, zn, o);

    // group mins
    float gmv[8];
    float m = 3.4e38f;
#pragma unroll
    for (int i = 0; i < 8; i++) {
        gmv[i] = g_gmin[(size_t)n * 256 + lane + 32 * i];
        m = fminf(m, gmv[i]);
    }
#pragma unroll
    for (int o = 16; o > 0; o >>= 1) m = fminf(m, __shfl_xor_sync(0xffffffffu, m, o));
    float thr = m + TAU;

    float bd = 3.4e38f;
    int bi = 0x7fffffff;
    for (int g = 0; g < 256; g++) {
        float vg = __shfl_sync(0xffffffffu, gmv[g >> 5], g & 31);
        if (vg > thr) continue;
        // exact rescan of 32 codes, ascending k (first-index tiebreak via strict <)
        for (int kk = 0; kk < 32; kk++) {
            int k = g * 32 + kk;
            const float* er = emb + (size_t)k * Dk;
            float s = 0.f;
#pragma unroll
            for (int i = 0; i < 8; i++) s = fmaf(zr[i], er[lane + 32 * i], s);
#pragma unroll
            for (int o = 16; o > 0; o >>= 1) s += __shfl_xor_sync(0xffffffffu, s, o);
            float s1 = zn + g_enorm[k];        // fl(zz + ee)  (reference formula)
            float d = s1 - 2.0f * s;           // fl(s1 - 2*dot); 2*dot exact
            if (d < bd) { bd = d; bi = k; }
        }
    }
    if (lane == 0) {
        g_idx[n] = bi;
        if (idx_out) idx_out[n] = (float)bi;
    }
}

// ---------------- gather quantized + loss partials ----------------
__global__ __launch_bounds__(1024)
void quant_loss_kernel(const float* __restrict__ z, const float* __restrict__ emb,
                       float* __restrict__ qout) {
    __shared__ float red[1024];
    int g = blockIdx.x * 1024 + threadIdx.x;
    int t = g & 2047;
    int d = (g >> 11) & 255;
    int b = g >> 19;
    int n = b * 2048 + t;
    float q = emb[(size_t)g_idx[n] * Dk + d];
    qout[g] = q;
    float diff = q - z[g];
    red[threadIdx.x] = diff * diff;
    __syncthreads();
#pragma unroll
    for (int o = 512; o > 0; o >>= 1) {
        if (threadIdx.x < o) red[threadIdx.x] += red[threadIdx.x + o];
        __syncthreads();
    }
    if (threadIdx.x == 0) g_losspart[blockIdx.x] = red[0];
}

__global__ void loss_kernel(float* __restrict__ loss_out) {
    __shared__ float red[256];
    float s = 0.f;
    for (int i = threadIdx.x; i < QCOUNT / 1024; i += 256) s += g_losspart[i];
    red[threadIdx.x] = s;
    __syncthreads();
#pragma unroll
    for (int o = 128; o > 0; o >>= 1) {
        if (threadIdx.x < o) red[threadIdx.x] += red[threadIdx.x + o];
        __syncthreads();
    }
    if (threadIdx.x == 0) loss_out[0] = 1.25f * (red[0] / (float)QCOUNT);
}

// ---------------- host launch ----------------
extern "C" void kernel_launch(void* const* d_in, const int* in_sizes, int n_in,
                              void* d_out, int out_size) {
    const float* z   = (const float*)d_in[0];
    const float* emb = (const float*)d_in[1];
    float* out = (float*)d_out;

    float* qout     = out;
    float* loss_out = nullptr;
    float* idx_out  = nullptr;
    if (out_size >= QCOUNT + 1 + Nk) {          // [quantized | loss | idx]
        loss_out = out + QCOUNT;
        idx_out  = out + QCOUNT + 1;
    } else if (out_size == QCOUNT + Nk) {
        idx_out = out + QCOUNT;
    } else if (out_size == QCOUNT + 1) {
        loss_out = out + QCOUNT;
    }

    static bool attr_set = false;
    if (!attr_set) {
        cudaFuncSetAttribute(pass1_gemm, cudaFuncAttributeMaxDynamicSharedMemorySize, SMEM_TOTAL);
        attr_set = true;
    }

    enorm_kernel<<<Kk / 8, 256>>>(emb);
    prepA_kernel<<<dim3(Bk * (Tk / 32), Dk / 32), dim3(32, 8)>>>(z);
    prepB_kernel<<<(Kk * Dk) / 256, 256>>>(emb);
    pass1_gemm<<<Nk / GM, 256, SMEM_TOTAL>>>();
    refine_kernel<<<Nk / 8, 256>>>(emb, idx_out);
    quant_loss_kernel<<<QCOUNT / 1024, 1024>>>(z, emb, qout);
    if (loss_out) loss_kernel<<<1, 256>>>(loss_out);
}